// round 14
// baseline (speedup 1.0000x reference)
#include <cuda_runtime.h>
#include <math.h>

#define NN 128
#define PITCHD 130   // float2 pitch: conflict-free LDS row reads
#define BATCH 512
#define NPAIRS 8128
#define NT 512
#define SEGJ 32
#define TSTEPS 10

typedef unsigned long long ull;

struct __align__(16) Smem {
  float2 DW[NN * PITCHD];   // (d,w) pairs, row-major, symmetric
  float4 Xs[NN];            // coordinates, .w = |x|^2
  float4 part[3 * NN];      // cross-group partials (phase B only)
  float  xsX[NN];           // SoA copies of X
  float  xsY[NN];
  float  xsZ[NN];
  float  xsW[NN];
  unsigned bits[NN * 4];    // adjacency bitmask
  float rs[NN];             // row sums of D^2
  float u0[NN];             // power-iteration ping
  float u1[NN];             // power-iteration pong
  float scal[8];
  int icnt[4];
};

__device__ __forceinline__ float softplus_f(float x) {
  return fmaxf(x, 0.0f) + __logf(1.0f + __expf(-fabsf(x)));
}
__device__ __forceinline__ ull pk2(float lo, float hi) {
  ull r; asm("mov.b64 %0, {%1, %2};" : "=l"(r) : "f"(lo), "f"(hi)); return r;
}
__device__ __forceinline__ void upk2(ull v, float& lo, float& hi) {
  asm("mov.b64 {%0, %1}, %2;" : "=f"(lo), "=f"(hi) : "l"(v));
}
__device__ __forceinline__ ull fma2(ull a, ull b, ull c) {
  ull d; asm("fma.rn.f32x2 %0, %1, %2, %3;" : "=l"(d) : "l"(a), "l"(b), "l"(c));
  return d;
}
__device__ __forceinline__ ull add2(ull a, ull b) {
  ull d; asm("add.rn.f32x2 %0, %1, %2;" : "=l"(d) : "l"(a), "l"(b));
  return d;
}

__global__ void __launch_bounds__(NT, 1)
ts_gcn_kernel(const float* __restrict__ edge_pred,
              const int*   __restrict__ adj,
              const float* __restrict__ d_init,
              const float* __restrict__ u_init,
              const float* __restrict__ x_noise,
              float*       __restrict__ out)
{
  extern __shared__ __align__(16) char smem_raw[];
  Smem* sm = reinterpret_cast<Smem*>(smem_raw);
  const int b    = blockIdx.x;
  const int tid  = threadIdx.x;
  const int lane = tid & 31;
  const int wid  = tid >> 5;
  const int i_d  = tid & (NN - 1);   // old mapping (phases A/B/E)
  const int g    = tid >> 7;
  const int j0   = g * SEGJ;
  // warp-owns-rows mapping (phases B2/C/preload/D)
  const int row  = (wid << 3) + (lane & 7);   // 16 warps x 8 rows = 128
  const int seg  = lane >> 3;                 // 0..3
  const int j0n  = seg * SEGJ;
  const float d0 = __ldg(d_init);

  const float4* epb4 = reinterpret_cast<const float4*>(edge_pred)
                       + (size_t)b * NN * NN / 2;
  const int*    adjb = adj + (size_t)b * NN * NN;

  if (tid == 0) sm->icnt[0] = 0;

  // ---- A1: stage raw edge_pred (LDG.128 -> STS.128, coalesced) ----------------
  #pragma unroll
  for (int v = 0; v < 16; ++v) {
    int idx4 = v * NT + tid;               // 8192 float4 chunks
    int r = idx4 >> 6;                     // 64 float4 per row
    int c4 = idx4 & 63;
    *reinterpret_cast<float4*>(&sm->DW[r * PITCHD + c4 * 2]) = epb4[idx4];
  }
  // ---- A1b: adjacency bits via ballot -----------------------------------------
  #pragma unroll
  for (int v = 0; v < 32; ++v) {
    int word = v * 16 + wid;
    int i = word >> 2, q = word & 3;
    int a = adjb[i * NN + q * 32 + lane];
    unsigned m = __ballot_sync(0xffffffffu, a != 0);
    if (lane == 0) sm->bits[word] = m;
  }
  __syncthreads();

  // ---- A2: symmetrize + softplus over upper triangle --------------------------
  #pragma unroll
  for (int v = 0; v < 16; ++v) {
    int p = v * NT + tid;
    if (p < NPAIRS) {
      int r = p / 127, c = p - r * 127;
      int i, j;
      if (c >= r) { i = r; j = c + 1; }
      else        { i = 127 - r; j = 127 - c; }
      unsigned on = (sm->bits[(i << 2) + (j >> 5)] >> (j & 31)) & 1u;
      float2 e1 = sm->DW[i * PITCHD + j];
      float2 e2 = sm->DW[j * PITCHD + i];
      float2 dw = make_float2(0.0f, 0.0f);
      if (on) {
        dw.x = softplus_f(d0 + e1.x + e2.x);
        dw.y = softplus_f(d0 + e1.y + e2.y);
      }
      sm->DW[i * PITCHD + j] = dw;
      sm->DW[j * PITCHD + i] = dw;
    }
  }
  if (tid < NN) sm->DW[tid * PITCHD + tid] = make_float2(0.0f, 0.0f);
  __syncthreads();

  // ---- B: sum(adj) + row sums of D^2 (old mapping) -----------------------------
  {
    int cbit = __popc(sm->bits[tid]);
    #pragma unroll
    for (int o = 16; o; o >>= 1) cbit += __shfl_xor_sync(0xffffffffu, cbit, o);
    if (lane == 0) atomicAdd(&sm->icnt[0], cbit);
  }
  {
    float rp = 0.0f;
    const float4* drow = reinterpret_cast<const float4*>(sm->DW + i_d * PITCHD + j0);
    #pragma unroll
    for (int t = 0; t < 16; ++t) {
      float4 q = drow[t];
      rp = fmaf(q.x, q.x, rp);
      rp = fmaf(q.z, q.z, rp);
    }
    if (g) sm->part[(g - 1) * NN + i_d].x = rp;
    __syncthreads();
    if (g == 0) {
      rp += sm->part[i_d].x + sm->part[NN + i_d].x + sm->part[2 * NN + i_d].x;
      sm->rs[i_d] = rp;
    }
  }
  __syncthreads();
  if (tid < 32) {
    float m = sm->rs[tid] + sm->rs[tid + 32] + sm->rs[tid + 64] + sm->rs[tid + 96];
    #pragma unroll
    for (int o = 16; o; o >>= 1) m += __shfl_xor_sync(0xffffffffu, m, o);
    if (tid == 0) {
      float Nmol = 1.0f + (float)(__popc(sm->bits[0]) + __popc(sm->bits[1]) +
                                  __popc(sm->bits[2]) + __popc(sm->bits[3]));
      float invN = 1.0f / Nmol;
      sm->scal[0] = invN;
      sm->scal[1] = m * invN * invN;
      float S = 128.0f + (float)sm->icnt[0];
      sm->scal[2] = 0.4f / S;
    }
  }
  __syncthreads();

  // ---- B2: Gram matrix into registers (row, j0n mapping) -----------------------
  float bg[SEGJ];
  {
    float invN = sm->scal[0], Moff = sm->scal[1];
    float rsi = sm->rs[row];
    unsigned wb = sm->bits[(row << 2) + seg];
    const float4* drow = reinterpret_cast<const float4*>(sm->DW + row * PITCHD + j0n);
    const float4* rsj  = reinterpret_cast<const float4*>(sm->rs + j0n);
    #pragma unroll
    for (int t = 0; t < 8; ++t) {
      float4 rq = rsj[t];
      float4 q0 = drow[2 * t], q1 = drow[2 * t + 1];
      float dv[4] = {q0.x, q0.z, q1.x, q1.z};
      float rv[4] = {rq.x, rq.y, rq.z, rq.w};
      #pragma unroll
      for (int m = 0; m < 4; ++m) {
        int jj = 4 * t + m;
        int j = j0n + jj;
        bool on = (((wb >> jj) & 1u) != 0u) || (j == row);
        float val = -0.5f * (fmaf(dv[m], dv[m], Moff) - (rsi + rv[m]) * invN);
        bg[jj] = on ? val : 0.0f;
      }
    }
  }

  // ---- C: rank-3 power iteration, normalization-free, 1 barrier/iter -----------
  for (int k = 0; k < 3; ++k) {
    __syncthreads();
    if (tid < NN) sm->u0[tid] = u_init[((size_t)b * NN + tid) * 3 + k];
    __syncthreads();
    #pragma unroll
    for (int it = 0; it < 10; ++it) {
      const float* uc = (it & 1) ? sm->u1 : sm->u0;
      float*       un = (it & 1) ? sm->u0 : sm->u1;
      float a0 = 0.f, a1 = 0.f, a2 = 0.f, a3 = 0.f;
      const float4* useg = reinterpret_cast<const float4*>(uc + j0n);
      #pragma unroll
      for (int t = 0; t < 8; ++t) {
        float4 uq = useg[t];
        a0 = fmaf(bg[4 * t + 0], uq.x, a0);
        a1 = fmaf(bg[4 * t + 1], uq.y, a1);
        a2 = fmaf(bg[4 * t + 2], uq.z, a2);
        a3 = fmaf(bg[4 * t + 3], uq.w, a3);
      }
      float acc = (a0 + a1) + (a2 + a3);
      acc += __shfl_xor_sync(0xffffffffu, acc, 8);
      acc += __shfl_xor_sync(0xffffffffu, acc, 16);
      if (lane < 8) un[row] = acc * 0.00390625f;   // 2^-8 rescale
      __syncthreads();
    }
    // after 10 iters: w10 in u0, w9 in u1
    float4 v0 = reinterpret_cast<const float4*>(sm->u0)[lane];
    float4 v1 = reinterpret_cast<const float4*>(sm->u1)[lane];
    float n10 = fmaf(v0.x, v0.x, fmaf(v0.y, v0.y, fmaf(v0.z, v0.z, v0.w * v0.w)));
    float n9  = fmaf(v1.x, v1.x, fmaf(v1.y, v1.y, fmaf(v1.z, v1.z, v1.w * v1.w)));
    #pragma unroll
    for (int o = 16; o; o >>= 1) {
      n10 += __shfl_xor_sync(0xffffffffu, n10, o);
      n9  += __shfl_xor_sync(0xffffffffu, n9, o);
    }
    float eig = 65536.0f * n10 / n9;
    float f = 256.0f * rsqrtf(n9) * rsqrtf(sqrtf(eig + 0.01f));
    __syncthreads();
    if (lane < 8) {
      float uf = sm->u0[row] * f;
      sm->u1[row] = uf;                              // u_final
      reinterpret_cast<float*>(&sm->Xs[row])[k] =
          uf + x_noise[((size_t)b * NN + row) * 3 + k];
    }
    __syncthreads();
    if (k < 2) {   // deflate: bg -= uf uf^T
      float ui = sm->u1[row];
      const float4* us = reinterpret_cast<const float4*>(sm->u1 + j0n);
      #pragma unroll
      for (int t = 0; t < 8; ++t) {
        float4 uq = us[t];
        bg[4 * t + 0] = fmaf(-ui, uq.x, bg[4 * t + 0]);
        bg[4 * t + 1] = fmaf(-ui, uq.y, bg[4 * t + 1]);
        bg[4 * t + 2] = fmaf(-ui, uq.z, bg[4 * t + 2]);
        bg[4 * t + 3] = fmaf(-ui, uq.w, bg[4 * t + 3]);
      }
    }
  }
  __syncthreads();
  // finalize Xs.w = |x|^2 and SoA copies
  if (tid < NN) {
    float4 x = sm->Xs[tid];
    x.w = fmaf(x.x, x.x, fmaf(x.y, x.y, x.z * x.z));
    sm->Xs[tid] = x;
    sm->xsX[tid] = x.x; sm->xsY[tid] = x.y;
    sm->xsZ[tid] = x.z; sm->xsW[tid] = x.w;
  }

  // ---- preload packed (w*d) and (-w) -------------------------------------------
  ull wd2[SEGJ / 2], wn2[SEGJ / 2];
  {
    const float4* drow = reinterpret_cast<const float4*>(sm->DW + row * PITCHD + j0n);
    #pragma unroll
    for (int t = 0; t < 16; ++t) {
      float4 q = drow[t];                    // (d0,w0,d1,w1)
      wd2[t] = pk2(q.x * q.y, q.z * q.w);
      wn2[t] = pk2(-q.y, -q.w);
    }
  }
  const float cc = sm->scal[2];
  __syncthreads();

  // ---- D: 10 gradient steps, float4 SoA loads (half the LDS), f32x2 math -------
  for (int ts = 0; ts < TSTEPS; ++ts) {
    float alpha = 0.1f + 4.9f * ((float)(TSTEPS - ts) * 0.1f);
    float xix = sm->xsX[row], xiy = sm->xsY[row];
    float xiz = sm->xsZ[row], xiw = sm->xsW[row];
    ull m2x2 = pk2(-2.0f * xix, -2.0f * xix);
    ull m2y2 = pk2(-2.0f * xiy, -2.0f * xiy);
    ull m2z2 = pk2(-2.0f * xiz, -2.0f * xiz);
    float cbase = xiw + 0.01f;
    ull cbase2 = pk2(cbase, cbase);
    ull cs2 = 0ull, ax2 = 0ull, ay2 = 0ull, az2 = 0ull;
    const float4* pX4 = reinterpret_cast<const float4*>(sm->xsX + j0n);
    const float4* pY4 = reinterpret_cast<const float4*>(sm->xsY + j0n);
    const float4* pZ4 = reinterpret_cast<const float4*>(sm->xsZ + j0n);
    const float4* pW4 = reinterpret_cast<const float4*>(sm->xsW + j0n);
    #pragma unroll
    for (int t = 0; t < 8; ++t) {            // 4 j's per iteration
      float4 qx = pX4[t], qy = pY4[t], qz = pZ4[t], qw = pW4[t];
      ull xjx0 = pk2(qx.x, qx.y), xjx1 = pk2(qx.z, qx.w);
      ull xjy0 = pk2(qy.x, qy.y), xjy1 = pk2(qy.z, qy.w);
      ull xjz0 = pk2(qz.x, qz.y), xjz1 = pk2(qz.z, qz.w);
      ull xjw0 = pk2(qw.x, qw.y), xjw1 = pk2(qw.z, qw.w);
      // chain 0: j = 4t, 4t+1
      ull s2p0 = fma2(xjx0, m2x2, xjw0);
      s2p0 = fma2(xjy0, m2y2, s2p0);
      s2p0 = fma2(xjz0, m2z2, s2p0);
      s2p0 = add2(s2p0, cbase2);
      float sa, sb;
      upk2(s2p0, sa, sb);
      ull r20 = pk2(rsqrtf(sa), rsqrtf(sb));
      ull coef0 = fma2(wd2[2 * t], r20, wn2[2 * t]);
      cs2 = add2(cs2, coef0);
      ax2 = fma2(coef0, xjx0, ax2);
      ay2 = fma2(coef0, xjy0, ay2);
      az2 = fma2(coef0, xjz0, az2);
      // chain 1: j = 4t+2, 4t+3
      ull s2p1 = fma2(xjx1, m2x2, xjw1);
      s2p1 = fma2(xjy1, m2y2, s2p1);
      s2p1 = fma2(xjz1, m2z2, s2p1);
      s2p1 = add2(s2p1, cbase2);
      float sc_, sd;
      upk2(s2p1, sc_, sd);
      ull r21 = pk2(rsqrtf(sc_), rsqrtf(sd));
      ull coef1 = fma2(wd2[2 * t + 1], r21, wn2[2 * t + 1]);
      cs2 = add2(cs2, coef1);
      ax2 = fma2(coef1, xjx1, ax2);
      ay2 = fma2(coef1, xjy1, ay2);
      az2 = fma2(coef1, xjz1, az2);
    }
    float csl, csh, axl, axh, ayl, ayh, azl, azh;
    upk2(cs2, csl, csh); upk2(ax2, axl, axh);
    upk2(ay2, ayl, ayh); upk2(az2, azl, azh);
    float cs = csl + csh, ax = axl + axh, ay = ayl + ayh, az = azl + azh;
    cs += __shfl_xor_sync(0xffffffffu, cs, 8);
    ax += __shfl_xor_sync(0xffffffffu, ax, 8);
    ay += __shfl_xor_sync(0xffffffffu, ay, 8);
    az += __shfl_xor_sync(0xffffffffu, az, 8);
    cs += __shfl_xor_sync(0xffffffffu, cs, 16);
    ax += __shfl_xor_sync(0xffffffffu, ax, 16);
    ay += __shfl_xor_sync(0xffffffffu, ay, 16);
    az += __shfl_xor_sync(0xffffffffu, az, 16);
    if (lane < 8) {
      float gx = fmaf(cs, xix, -ax) * cc;
      float gy = fmaf(cs, xiy, -ay) * cc;
      float gz = fmaf(cs, xiz, -az) * cc;
      float s2 = fmaf(gx, gx, fmaf(gy, gy, fmaf(gz, gz, 0.001f)));
      float inv_sp = rsqrtf(s2);
      float sp = s2 * inv_sp;
      float e = __expf(2.0f * (sp / alpha));
      float th = 1.0f - __fdividef(2.0f, e + 1.0f);   // tanh(sp/alpha)
      float sc = alpha * th * inv_sp;
      float nx = fmaf(gx, sc, xix);
      float ny = fmaf(gy, sc, xiy);
      float nz = fmaf(gz, sc, xiz);
      float nw = fmaf(nx, nx, fmaf(ny, ny, nz * nz));
      sm->xsX[row] = nx; sm->xsY[row] = ny;
      sm->xsZ[row] = nz; sm->xsW[row] = nw;
      sm->Xs[row] = make_float4(nx, ny, nz, nw);
    }
    __syncthreads();
  }

  // ---- E: output = adj * distances(X); sqrt via s*rsqrt(s) ----------------------
  float* outb = out + (size_t)b * NN * NN;
  #pragma unroll
  for (int v = 0; v < 8; ++v) {
    int f = v * NT + tid;
    int i = f >> 5;
    int jb = (f & 31) * 4;
    float4 xi = sm->Xs[i];
    unsigned wb = sm->bits[(i << 2) + (jb >> 5)];
    float4 r;
    #pragma unroll
    for (int m = 0; m < 4; ++m) {
      int j = jb + m;
      float4 xj = sm->Xs[j];
      float dx = xi.x - xj.x, dy = xi.y - xj.y, dz = xi.z - xj.z;
      float s = fmaf(dx, dx, fmaf(dy, dy, fmaf(dz, dz, 0.01f)));
      float val = ((wb >> (j & 31)) & 1u) ? s * rsqrtf(s) : 0.0f;
      reinterpret_cast<float*>(&r)[m] = val;
    }
    reinterpret_cast<float4*>(outb)[f] = r;
  }
}

extern "C" void kernel_launch(void* const* d_in, const int* in_sizes, int n_in,
                              void* d_out, int out_size) {
  const float* edge_pred = (const float*)d_in[0];
  const int*   adj       = (const int*)  d_in[1];
  const float* d_init    = (const float*)d_in[2];
  const float* u_init    = (const float*)d_in[3];
  const float* x_noise   = (const float*)d_in[4];
  float* out = (float*)d_out;

  size_t smem = sizeof(Smem);
  cudaFuncSetAttribute(ts_gcn_kernel,
                       cudaFuncAttributeMaxDynamicSharedMemorySize, (int)smem);
  ts_gcn_kernel<<<BATCH, NT, smem>>>(edge_pred, adj, d_init, u_init,
                                     x_noise, out);
}

// round 15
// speedup vs baseline: 1.0256x; 1.0256x over previous
#include <cuda_runtime.h>
#include <math.h>

#define NN 128
#define PITCHD 130   // float2 pitch: conflict-free LDS row reads
#define BATCH 512
#define NPAIRS 8128
#define NT 512
#define SEGJ 32
#define TSTEPS 10

typedef unsigned long long ull;

struct __align__(16) Smem {
  float2 DW[NN * PITCHD];   // (d,w) pairs, row-major, symmetric
  float4 Xs[NN];            // coordinates, .w = |x|^2
  float4 part[3 * NN];      // cross-group partials (phase B only)
  float  xsX[NN];           // SoA copies of X
  float  xsY[NN];
  float  xsZ[NN];
  float  xsW[NN];
  unsigned bits[NN * 4];    // adjacency bitmask
  float rs[NN];             // row sums of D^2
  float u0[NN];             // power-iteration ping
  float u1[NN];             // power-iteration pong
  float uin[3 * NN];        // prefetched u_init columns
  float xn[3 * NN];         // prefetched x_noise columns
  float scal[8];
  int icnt[4];
};

__device__ __forceinline__ float softplus_f(float x) {
  return fmaxf(x, 0.0f) + __logf(1.0f + __expf(-fabsf(x)));
}
__device__ __forceinline__ ull pk2(float lo, float hi) {
  ull r; asm("mov.b64 %0, {%1, %2};" : "=l"(r) : "f"(lo), "f"(hi)); return r;
}
__device__ __forceinline__ void upk2(ull v, float& lo, float& hi) {
  asm("mov.b64 {%0, %1}, %2;" : "=f"(lo), "=f"(hi) : "l"(v));
}
__device__ __forceinline__ ull fma2(ull a, ull b, ull c) {
  ull d; asm("fma.rn.f32x2 %0, %1, %2, %3;" : "=l"(d) : "l"(a), "l"(b), "l"(c));
  return d;
}
__device__ __forceinline__ ull add2(ull a, ull b) {
  ull d; asm("add.rn.f32x2 %0, %1, %2;" : "=l"(d) : "l"(a), "l"(b));
  return d;
}

__global__ void __launch_bounds__(NT, 1)
ts_gcn_kernel(const float* __restrict__ edge_pred,
              const int*   __restrict__ adj,
              const float* __restrict__ d_init,
              const float* __restrict__ u_init,
              const float* __restrict__ x_noise,
              float*       __restrict__ out)
{
  extern __shared__ __align__(16) char smem_raw[];
  Smem* sm = reinterpret_cast<Smem*>(smem_raw);
  const int b    = blockIdx.x;
  const int tid  = threadIdx.x;
  const int lane = tid & 31;
  const int wid  = tid >> 5;
  const int i_d  = tid & (NN - 1);   // old mapping (phases A/B/E)
  const int g    = tid >> 7;
  const int j0   = g * SEGJ;
  // warp-owns-rows mapping (phases B2/C/preload/D)
  const int row  = (wid << 3) + (lane & 7);   // 16 warps x 8 rows = 128
  const int seg  = lane >> 3;                 // 0..3
  const int j0n  = seg * SEGJ;
  const float d0 = __ldg(d_init);

  const float2* epb  = reinterpret_cast<const float2*>(edge_pred) + (size_t)b * NN * NN;
  const int*    adjb = adj + (size_t)b * NN * NN;

  if (tid == 0) sm->icnt[0] = 0;

  // ---- A0: prefetch u_init / x_noise columns into smem (coalesced) ------------
  {
    // q = 3*i + k  ->  store col-major uin[k*NN + i]
    if (tid < 3 * NN) {
      float v = u_init[(size_t)b * 3 * NN + tid];
      int k = tid % 3, i = tid / 3;
      sm->uin[k * NN + i] = v;
    }
    int q = tid + NT - 3 * NN;   // threads 384..511 -> q = 512..639? no: reuse all
    (void)q;
    // second pass covers x_noise with all threads
    for (int base = tid; base < 3 * NN; base += NT) {
      float v = x_noise[(size_t)b * 3 * NN + base];
      int k = base % 3, i = base / 3;
      sm->xn[k * NN + i] = v;
    }
  }

  // ---- A1: stage raw edge_pred (coalesced) -----------------------------------
  #pragma unroll
  for (int v = 0; v < 32; ++v) {
    int idx = v * NT + tid;
    sm->DW[(idx >> 7) * PITCHD + (idx & (NN - 1))] = epb[idx];
  }
  // ---- A1b: adjacency bits via ballot -----------------------------------------
  #pragma unroll
  for (int v = 0; v < 32; ++v) {
    int word = v * 16 + wid;
    int i = word >> 2, q = word & 3;
    int a = adjb[i * NN + q * 32 + lane];
    unsigned m = __ballot_sync(0xffffffffu, a != 0);
    if (lane == 0) sm->bits[word] = m;
  }
  __syncthreads();

  // ---- A2: symmetrize + softplus over upper triangle --------------------------
  #pragma unroll
  for (int v = 0; v < 16; ++v) {
    int p = v * NT + tid;
    if (p < NPAIRS) {
      int r = p / 127, c = p - r * 127;
      int i, j;
      if (c >= r) { i = r; j = c + 1; }
      else        { i = 127 - r; j = 127 - c; }
      unsigned on = (sm->bits[(i << 2) + (j >> 5)] >> (j & 31)) & 1u;
      float2 e1 = sm->DW[i * PITCHD + j];
      float2 e2 = sm->DW[j * PITCHD + i];
      float2 dw = make_float2(0.0f, 0.0f);
      if (on) {
        dw.x = softplus_f(d0 + e1.x + e2.x);
        dw.y = softplus_f(d0 + e1.y + e2.y);
      }
      sm->DW[i * PITCHD + j] = dw;
      sm->DW[j * PITCHD + i] = dw;
    }
  }
  if (tid < NN) sm->DW[tid * PITCHD + tid] = make_float2(0.0f, 0.0f);
  __syncthreads();

  // ---- B: sum(adj) + row sums of D^2 (old mapping) -----------------------------
  {
    int cbit = __popc(sm->bits[tid]);
    #pragma unroll
    for (int o = 16; o; o >>= 1) cbit += __shfl_xor_sync(0xffffffffu, cbit, o);
    if (lane == 0) atomicAdd(&sm->icnt[0], cbit);
  }
  {
    float rp = 0.0f;
    const float4* drow = reinterpret_cast<const float4*>(sm->DW + i_d * PITCHD + j0);
    #pragma unroll
    for (int t = 0; t < 16; ++t) {
      float4 q = drow[t];
      rp = fmaf(q.x, q.x, rp);
      rp = fmaf(q.z, q.z, rp);
    }
    if (g) sm->part[(g - 1) * NN + i_d].x = rp;
    __syncthreads();
    if (g == 0) {
      rp += sm->part[i_d].x + sm->part[NN + i_d].x + sm->part[2 * NN + i_d].x;
      sm->rs[i_d] = rp;
    }
  }
  __syncthreads();
  if (tid < 32) {
    float m = sm->rs[tid] + sm->rs[tid + 32] + sm->rs[tid + 64] + sm->rs[tid + 96];
    #pragma unroll
    for (int o = 16; o; o >>= 1) m += __shfl_xor_sync(0xffffffffu, m, o);
    if (tid == 0) {
      float Nmol = 1.0f + (float)(__popc(sm->bits[0]) + __popc(sm->bits[1]) +
                                  __popc(sm->bits[2]) + __popc(sm->bits[3]));
      float invN = 1.0f / Nmol;
      sm->scal[0] = invN;
      sm->scal[1] = m * invN * invN;
      float S = 128.0f + (float)sm->icnt[0];
      sm->scal[2] = 0.4f / S;
    }
  }
  __syncthreads();

  // ---- B2: Gram matrix into registers (row, j0n mapping) -----------------------
  float bg[SEGJ];
  {
    float invN = sm->scal[0], Moff = sm->scal[1];
    float rsi = sm->rs[row];
    unsigned wb = sm->bits[(row << 2) + seg];
    const float4* drow = reinterpret_cast<const float4*>(sm->DW + row * PITCHD + j0n);
    const float4* rsj  = reinterpret_cast<const float4*>(sm->rs + j0n);
    #pragma unroll
    for (int t = 0; t < 8; ++t) {
      float4 rq = rsj[t];
      float4 q0 = drow[2 * t], q1 = drow[2 * t + 1];
      float dv[4] = {q0.x, q0.z, q1.x, q1.z};
      float rv[4] = {rq.x, rq.y, rq.z, rq.w};
      #pragma unroll
      for (int m = 0; m < 4; ++m) {
        int jj = 4 * t + m;
        int j = j0n + jj;
        bool on = (((wb >> jj) & 1u) != 0u) || (j == row);
        float val = -0.5f * (fmaf(dv[m], dv[m], Moff) - (rsi + rv[m]) * invN);
        bg[jj] = on ? val : 0.0f;
      }
    }
  }

  // ---- C: rank-3 power iteration, normalization-free, 1 barrier/iter -----------
  for (int k = 0; k < 3; ++k) {
    // (no loop-top barrier: all u0 reads of the previous k complete before the
    //  uf-write barrier at the end of that k)
    if (tid < NN) sm->u0[tid] = sm->uin[k * NN + tid];
    __syncthreads();
    #pragma unroll
    for (int it = 0; it < 10; ++it) {
      const float* uc = (it & 1) ? sm->u1 : sm->u0;
      float*       un = (it & 1) ? sm->u0 : sm->u1;
      float a0 = 0.f, a1 = 0.f, a2 = 0.f, a3 = 0.f;
      const float4* useg = reinterpret_cast<const float4*>(uc + j0n);
      #pragma unroll
      for (int t = 0; t < 8; ++t) {
        float4 uq = useg[t];
        a0 = fmaf(bg[4 * t + 0], uq.x, a0);
        a1 = fmaf(bg[4 * t + 1], uq.y, a1);
        a2 = fmaf(bg[4 * t + 2], uq.z, a2);
        a3 = fmaf(bg[4 * t + 3], uq.w, a3);
      }
      float acc = (a0 + a1) + (a2 + a3);
      acc += __shfl_xor_sync(0xffffffffu, acc, 8);
      acc += __shfl_xor_sync(0xffffffffu, acc, 16);
      if (lane < 8) un[row] = acc * 0.00390625f;   // 2^-8 rescale
      __syncthreads();
    }
    // after 10 iters: w10 in u0, w9 in u1
    float4 v0 = reinterpret_cast<const float4*>(sm->u0)[lane];
    float4 v1 = reinterpret_cast<const float4*>(sm->u1)[lane];
    float n10 = fmaf(v0.x, v0.x, fmaf(v0.y, v0.y, fmaf(v0.z, v0.z, v0.w * v0.w)));
    float n9  = fmaf(v1.x, v1.x, fmaf(v1.y, v1.y, fmaf(v1.z, v1.z, v1.w * v1.w)));
    #pragma unroll
    for (int o = 16; o; o >>= 1) {
      n10 += __shfl_xor_sync(0xffffffffu, n10, o);
      n9  += __shfl_xor_sync(0xffffffffu, n9, o);
    }
    float eig = 65536.0f * n10 / n9;
    float f = 256.0f * rsqrtf(n9) * rsqrtf(sqrtf(eig + 0.01f));
    __syncthreads();
    if (lane < 8) {
      float uf = sm->u0[row] * f;
      sm->u1[row] = uf;                              // u_final
      reinterpret_cast<float*>(&sm->Xs[row])[k] = uf + sm->xn[k * NN + row];
    }
    __syncthreads();
    if (k < 2) {   // deflate: bg -= uf uf^T
      float ui = sm->u1[row];
      const float4* us = reinterpret_cast<const float4*>(sm->u1 + j0n);
      #pragma unroll
      for (int t = 0; t < 8; ++t) {
        float4 uq = us[t];
        bg[4 * t + 0] = fmaf(-ui, uq.x, bg[4 * t + 0]);
        bg[4 * t + 1] = fmaf(-ui, uq.y, bg[4 * t + 1]);
        bg[4 * t + 2] = fmaf(-ui, uq.z, bg[4 * t + 2]);
        bg[4 * t + 3] = fmaf(-ui, uq.w, bg[4 * t + 3]);
      }
    }
  }
  __syncthreads();
  // finalize Xs.w = |x|^2 and SoA copies
  if (tid < NN) {
    float4 x = sm->Xs[tid];
    x.w = fmaf(x.x, x.x, fmaf(x.y, x.y, x.z * x.z));
    sm->Xs[tid] = x;
    sm->xsX[tid] = x.x; sm->xsY[tid] = x.y;
    sm->xsZ[tid] = x.z; sm->xsW[tid] = x.w;
  }

  // ---- preload packed (w*d) and (-w) -------------------------------------------
  ull wd2[SEGJ / 2], wn2[SEGJ / 2];
  {
    const float4* drow = reinterpret_cast<const float4*>(sm->DW + row * PITCHD + j0n);
    #pragma unroll
    for (int t = 0; t < 16; ++t) {
      float4 q = drow[t];                    // (d0,w0,d1,w1)
      wd2[t] = pk2(q.x * q.y, q.z * q.w);
      wn2[t] = pk2(-q.y, -q.w);
    }
  }
  const float cc = sm->scal[2];
  __syncthreads();

  // ---- D: 10 gradient-descent steps, packed f32x2, 1 barrier/step --------------
  for (int ts = 0; ts < TSTEPS; ++ts) {
    float alpha = 0.1f + 4.9f * ((float)(TSTEPS - ts) * 0.1f);
    float xix = sm->xsX[row], xiy = sm->xsY[row];
    float xiz = sm->xsZ[row], xiw = sm->xsW[row];
    ull m2x2 = pk2(-2.0f * xix, -2.0f * xix);
    ull m2y2 = pk2(-2.0f * xiy, -2.0f * xiy);
    ull m2z2 = pk2(-2.0f * xiz, -2.0f * xiz);
    float cbase = xiw + 0.01f;
    ull cbase2 = pk2(cbase, cbase);
    ull cs2 = 0ull, ax2 = 0ull, ay2 = 0ull, az2 = 0ull;
    const ull* pX = reinterpret_cast<const ull*>(sm->xsX + j0n);
    const ull* pY = reinterpret_cast<const ull*>(sm->xsY + j0n);
    const ull* pZ = reinterpret_cast<const ull*>(sm->xsZ + j0n);
    const ull* pW = reinterpret_cast<const ull*>(sm->xsW + j0n);
    #pragma unroll
    for (int t = 0; t < SEGJ / 2; ++t) {
      ull xjx = pX[t], xjy = pY[t], xjz = pZ[t], xjw = pW[t];
      ull s2p = fma2(xjx, m2x2, xjw);
      s2p = fma2(xjy, m2y2, s2p);
      s2p = fma2(xjz, m2z2, s2p);
      s2p = add2(s2p, cbase2);               // |xi-xj|^2 + 0.01 (two j's)
      float s0, s1;
      upk2(s2p, s0, s1);
      ull r2 = pk2(rsqrtf(s0), rsqrtf(s1));
      ull coef2 = fma2(wd2[t], r2, wn2[t]);  // w*(d/Dx - 1)
      cs2 = add2(cs2, coef2);
      ax2 = fma2(coef2, xjx, ax2);
      ay2 = fma2(coef2, xjy, ay2);
      az2 = fma2(coef2, xjz, az2);
    }
    float csl, csh, axl, axh, ayl, ayh, azl, azh;
    upk2(cs2, csl, csh); upk2(ax2, axl, axh);
    upk2(ay2, ayl, ayh); upk2(az2, azl, azh);
    float cs = csl + csh, ax = axl + axh, ay = ayl + ayh, az = azl + azh;
    cs += __shfl_xor_sync(0xffffffffu, cs, 8);
    ax += __shfl_xor_sync(0xffffffffu, ax, 8);
    ay += __shfl_xor_sync(0xffffffffu, ay, 8);
    az += __shfl_xor_sync(0xffffffffu, az, 8);
    cs += __shfl_xor_sync(0xffffffffu, cs, 16);
    ax += __shfl_xor_sync(0xffffffffu, ax, 16);
    ay += __shfl_xor_sync(0xffffffffu, ay, 16);
    az += __shfl_xor_sync(0xffffffffu, az, 16);
    if (lane < 8) {
      float gx = fmaf(cs, xix, -ax) * cc;
      float gy = fmaf(cs, xiy, -ay) * cc;
      float gz = fmaf(cs, xiz, -az) * cc;
      float s2 = fmaf(gx, gx, fmaf(gy, gy, fmaf(gz, gz, 0.001f)));
      float inv_sp = rsqrtf(s2);
      float sp = s2 * inv_sp;
      float e = __expf(2.0f * (sp / alpha));
      float th = 1.0f - __fdividef(2.0f, e + 1.0f);   // tanh(sp/alpha)
      float sc = alpha * th * inv_sp;
      float nx = fmaf(gx, sc, xix);
      float ny = fmaf(gy, sc, xiy);
      float nz = fmaf(gz, sc, xiz);
      float nw = fmaf(nx, nx, fmaf(ny, ny, nz * nz));
      sm->xsX[row] = nx; sm->xsY[row] = ny;
      sm->xsZ[row] = nz; sm->xsW[row] = nw;
      sm->Xs[row] = make_float4(nx, ny, nz, nw);
    }
    __syncthreads();
  }

  // ---- E: output = adj * distances(X) -------------------------------------------
  float* outb = out + (size_t)b * NN * NN;
  #pragma unroll
  for (int v = 0; v < 8; ++v) {
    int f = v * NT + tid;
    int i = f >> 5;
    int jb = (f & 31) * 4;
    float4 xi = sm->Xs[i];
    unsigned wb = sm->bits[(i << 2) + (jb >> 5)];
    float4 r;
    #pragma unroll
    for (int m = 0; m < 4; ++m) {
      int j = jb + m;
      float4 xj = sm->Xs[j];
      float dx = xi.x - xj.x, dy = xi.y - xj.y, dz = xi.z - xj.z;
      float s = fmaf(dx, dx, fmaf(dy, dy, fmaf(dz, dz, 0.01f)));
      float val = ((wb >> (j & 31)) & 1u) ? sqrtf(s) : 0.0f;
      reinterpret_cast<float*>(&r)[m] = val;
    }
    reinterpret_cast<float4*>(outb)[f] = r;
  }
}

extern "C" void kernel_launch(void* const* d_in, const int* in_sizes, int n_in,
                              void* d_out, int out_size) {
  const float* edge_pred = (const float*)d_in[0];
  const int*   adj       = (const int*)  d_in[1];
  const float* d_init    = (const float*)d_in[2];
  const float* u_init    = (const float*)d_in[3];
  const float* x_noise   = (const float*)d_in[4];
  float* out = (float*)d_out;

  size_t smem = sizeof(Smem);
  cudaFuncSetAttribute(ts_gcn_kernel,
                       cudaFuncAttributeMaxDynamicSharedMemorySize, (int)smem);
  ts_gcn_kernel<<<BATCH, NT, smem>>>(edge_pred, adj, d_init, u_init,
                                     x_noise, out);
}